// round 2
// baseline (speedup 1.0000x reference)
#include <cuda_runtime.h>
#include <mma.h>
#include <math.h>

using namespace nvcuda;

#define N_TOK 8192
#define DIM   1024
#define HID   4096
#define NE    8
#define TOPK  2

// ---------------- device scratch (no allocations allowed) ----------------
__device__ int   g_counts[NE];
__device__ int   g_offsets[NE];
__device__ int   g_cursor[NE];
__device__ int   g_tok_e[N_TOK * TOPK];
__device__ float g_tok_w[N_TOK * TOPK];
__device__ int   g_btok[N_TOK * TOPK];
__device__ float g_bw[N_TOK * TOPK];
__device__ float g_h[(size_t)N_TOK * TOPK * HID];   // 256 MB hidden activations

// ---------------- init: zero output + counters ----------------
__global__ void init_kernel(float* __restrict__ out) {
    size_t i = (size_t)blockIdx.x * blockDim.x + threadIdx.x;
    if (i < (size_t)N_TOK * DIM / 4) {
        ((float4*)out)[i] = make_float4(0.f, 0.f, 0.f, 0.f);
    }
    if (blockIdx.x == 0 && threadIdx.x < NE) {
        g_counts[threadIdx.x] = 0;
        g_cursor[threadIdx.x] = 0;
    }
}

// ---------------- gating: warp per token ----------------
__global__ void gate_kernel(const float* __restrict__ x,
                            const float* __restrict__ gw,
                            const float* __restrict__ gb) {
    int warp = threadIdx.x >> 5;
    int lane = threadIdx.x & 31;
    int n = blockIdx.x * (blockDim.x >> 5) + warp;
    if (n >= N_TOK) return;

    float acc[NE];
#pragma unroll
    for (int e = 0; e < NE; e++) acc[e] = 0.f;

    const float* xr = x + (size_t)n * DIM;
    for (int d = lane; d < DIM; d += 32) {
        float xv = xr[d];
        float4 w0 = *(const float4*)(gw + (size_t)d * NE);
        float4 w1 = *(const float4*)(gw + (size_t)d * NE + 4);
        acc[0] += xv * w0.x; acc[1] += xv * w0.y;
        acc[2] += xv * w0.z; acc[3] += xv * w0.w;
        acc[4] += xv * w1.x; acc[5] += xv * w1.y;
        acc[6] += xv * w1.z; acc[7] += xv * w1.w;
    }
#pragma unroll
    for (int e = 0; e < NE; e++) {
#pragma unroll
        for (int o = 16; o; o >>= 1)
            acc[e] += __shfl_down_sync(0xffffffffu, acc[e], o);
    }

    if (lane == 0) {
        float v[NE];
#pragma unroll
        for (int e = 0; e < NE; e++) v[e] = acc[e] + gb[e];
        // top-2 (lowest index wins ties, matches top_k)
        int i0 = 0;
#pragma unroll
        for (int e = 1; e < NE; e++) if (v[e] > v[i0]) i0 = e;
        int i1 = -1;
#pragma unroll
        for (int e = 0; e < NE; e++) {
            if (e == i0) continue;
            if (i1 < 0 || v[e] > v[i1]) i1 = e;
        }
        // softmax over the 2 selected logits (v[i0] is the max)
        float t  = expf(v[i1] - v[i0]);
        float w0 = 1.f / (1.f + t);
        float w1 = t / (1.f + t);

        g_tok_e[n * 2]     = i0;
        g_tok_e[n * 2 + 1] = i1;
        g_tok_w[n * 2]     = w0;
        g_tok_w[n * 2 + 1] = w1;
        atomicAdd(&g_counts[i0], 1);
        atomicAdd(&g_counts[i1], 1);
    }
}

// ---------------- scan: exclusive prefix over 8 experts ----------------
__global__ void scan_kernel() {
    if (threadIdx.x == 0) {
        int s = 0;
        for (int e = 0; e < NE; e++) {
            g_offsets[e] = s;
            s += g_counts[e];
            g_cursor[e] = 0;
        }
    }
}

// ---------------- scatter tokens into per-expert buckets ----------------
__global__ void scatter_kernel() {
    int n = blockIdx.x * blockDim.x + threadIdx.x;
    if (n >= N_TOK) return;
#pragma unroll
    for (int k = 0; k < TOPK; k++) {
        int e = g_tok_e[n * 2 + k];
        int p = atomicAdd(&g_cursor[e], 1);
        int s = g_offsets[e] + p;
        g_btok[s] = n;
        g_bw[s]   = g_tok_w[n * 2 + k];
    }
}

// ---------------- grouped GEMM (tf32 wmma), 64x64x32 tiles ----------------
// MODE 0: h = gelu_tanh(gather(x) @ w1[e] + b1[e])     -> g_h
// MODE 1: out[token] += w * (h @ w2[e] + b2[e])        (atomic scatter)
#define BM  64
#define BN  64
#define BK  32
#define LDA 36
#define LDB 68
#define LDC 68

// smem: A[BM*LDA]=2304 + B[BK*LDB]=2176 -> 4480 floats; C reuse needs BM*LDC=4352
#define SMEM_FLOATS 4480

template <int MODE>
__global__ void __launch_bounds__(128)
expert_gemm(const float* __restrict__ X,     // x (mode0) / unused (mode1)
            const float* __restrict__ W,     // w1 or w2 base [E, Kdim, Ncols]
            const float* __restrict__ bias,  // b1 or b2 base [E, Ncols]
            float* __restrict__ out,         // final out (mode1)
            int Kdim, int Ncols) {
    int e    = blockIdx.z;
    int cnt  = g_counts[e];
    int row0 = blockIdx.y * BM;
    if (row0 >= cnt) return;
    int col0 = blockIdx.x * BN;
    int off  = g_offsets[e];
    const float* Wb = W + (size_t)e * Kdim * Ncols;

    __shared__ float smem[SMEM_FLOATS];
    float* sA = smem;                  // [BM][LDA] = 2304 floats
    float* sB = smem + BM * LDA;       // [BK][LDB] = 2176 floats
    float* sC = smem;                  // [BM][LDC] = 4352 floats (reused after k-loop)

    int tid  = threadIdx.x;
    int warp = tid >> 5;
    int wr   = warp >> 1;   // 0..1
    int wc   = warp & 1;    // 0..1

    wmma::fragment<wmma::accumulator, 16, 16, 8, float> acc[2][2];
#pragma unroll
    for (int i = 0; i < 2; i++)
#pragma unroll
        for (int j = 0; j < 2; j++)
            wmma::fill_fragment(acc[i][j], 0.f);

    for (int k0 = 0; k0 < Kdim; k0 += BK) {
        // load A tile 64x32 (gathered rows)
#pragma unroll
        for (int it = 0; it < 4; it++) {
            int idx = tid + it * 128;          // 0..511
            int r   = idx >> 3;                // row in tile
            int c4  = idx & 7;                 // float4 col
            int gr  = row0 + r;
            float4 v = make_float4(0.f, 0.f, 0.f, 0.f);
            if (gr < cnt) {
                const float* src;
                if (MODE == 0) {
                    int t = g_btok[off + gr];
                    src = X + (size_t)t * Kdim + k0 + c4 * 4;
                } else {
                    src = g_h + (size_t)(off + gr) * Kdim + k0 + c4 * 4;
                }
                v = *(const float4*)src;
            }
            *(float4*)&sA[r * LDA + c4 * 4] = v;
        }
        // load B tile 32x64
#pragma unroll
        for (int it = 0; it < 4; it++) {
            int idx = tid + it * 128;          // 0..511
            int r   = idx >> 4;                // 0..31
            int c4  = idx & 15;
            float4 v = *(const float4*)(Wb + (size_t)(k0 + r) * Ncols + col0 + c4 * 4);
            *(float4*)&sB[r * LDB + c4 * 4] = v;
        }
        __syncthreads();

#pragma unroll
        for (int kk = 0; kk < BK; kk += 8) {
            wmma::fragment<wmma::matrix_a, 16, 16, 8, wmma::precision::tf32, wmma::row_major> af[2];
            wmma::fragment<wmma::matrix_b, 16, 16, 8, wmma::precision::tf32, wmma::row_major> bf[2];
#pragma unroll
            for (int i = 0; i < 2; i++) {
                wmma::load_matrix_sync(af[i], &sA[(wr * 32 + i * 16) * LDA + kk], LDA);
#pragma unroll
                for (int t = 0; t < af[i].num_elements; t++)
                    af[i].x[t] = wmma::__float_to_tf32(af[i].x[t]);
            }
#pragma unroll
            for (int j = 0; j < 2; j++) {
                wmma::load_matrix_sync(bf[j], &sB[kk * LDB + wc * 32 + j * 16], LDB);
#pragma unroll
                for (int t = 0; t < bf[j].num_elements; t++)
                    bf[j].x[t] = wmma::__float_to_tf32(bf[j].x[t]);
            }
#pragma unroll
            for (int i = 0; i < 2; i++)
#pragma unroll
                for (int j = 0; j < 2; j++)
                    wmma::mma_sync(acc[i][j], af[i], bf[j], acc[i][j]);
        }
        __syncthreads();
    }

    // epilogue: stage C in smem, then bias (+gelu / +weighted scatter)
#pragma unroll
    for (int i = 0; i < 2; i++)
#pragma unroll
        for (int j = 0; j < 2; j++)
            wmma::store_matrix_sync(&sC[(wr * 32 + i * 16) * LDC + wc * 32 + j * 16],
                                    acc[i][j], LDC, wmma::mem_row_major);
    __syncthreads();

#pragma unroll
    for (int it = 0; it < 32; it++) {
        int idx = tid + it * 128;          // 0..4095
        int r   = idx >> 6;
        int c   = idx & 63;
        int gr  = row0 + r;
        if (gr >= cnt) continue;
        float v = sC[r * LDC + c] + bias[(size_t)e * Ncols + col0 + c];
        if (MODE == 0) {
            // jax.nn.gelu default: tanh approximation
            float u = v;
            float g = 0.5f * u * (1.f + tanhf(0.7978845608028654f * (u + 0.044715f * u * u * u)));
            g_h[(size_t)(off + gr) * Ncols + col0 + c] = g;
        } else {
            int   t = g_btok[off + gr];
            float w = g_bw[off + gr];
            atomicAdd(&out[(size_t)t * Ncols + col0 + c], w * v);
        }
    }
}

// ---------------- launch ----------------
extern "C" void kernel_launch(void* const* d_in, const int* in_sizes, int n_in,
                              void* d_out, int out_size) {
    (void)in_sizes; (void)n_in; (void)out_size;
    const float* x  = (const float*)d_in[0];
    const float* gw = (const float*)d_in[1];
    const float* gb = (const float*)d_in[2];
    const float* w1 = (const float*)d_in[3];
    const float* b1 = (const float*)d_in[4];
    const float* w2 = (const float*)d_in[5];
    const float* b2 = (const float*)d_in[6];
    float* out = (float*)d_out;

    init_kernel<<<(N_TOK * DIM / 4 + 255) / 256, 256>>>(out);
    gate_kernel<<<N_TOK / 8, 256>>>(x, gw, gb);
    scan_kernel<<<1, 32>>>();
    scatter_kernel<<<(N_TOK + 255) / 256, 256>>>();

    dim3 g1(HID / BN, N_TOK / BM, NE);
    expert_gemm<0><<<g1, 128>>>(x, w1, b1, out, DIM, HID);
    dim3 g2(DIM / BN, N_TOK / BM, NE);
    expert_gemm<1><<<g2, 128>>>(nullptr, w2, b2, out, HID, DIM);
}

// round 4
// speedup vs baseline: 1.0160x; 1.0160x over previous
#include <cuda_runtime.h>
#include <mma.h>
#include <math.h>

using namespace nvcuda;

#define N_TOK 8192
#define DIM   1024
#define HID   4096
#define NE    8
#define TOPK  2

// GEMM tiling
#define BM 128
#define BN 128
#define BK 32
#define LDA 36            // BK + 4 pad
#define LDB 132           // BN + 4 pad
#define LDC 132
#define STAGES 3
#define STAGE_FLOATS (BM * LDA + BK * LDB)   // 4608 + 4224 = 8832
#define GEMM_SMEM_BYTES (STAGES * STAGE_FLOATS * 4)  // 105984 B

// ---------------- device scratch (no allocations allowed) ----------------
__device__ int   g_counts[NE];
__device__ int   g_offsets[NE];
__device__ int   g_cursor[NE];
__device__ int   g_tok_e[N_TOK * TOPK];
__device__ float g_tok_w[N_TOK * TOPK];
__device__ int   g_btok[N_TOK * TOPK];
__device__ float g_bw[N_TOK * TOPK];
__device__ float g_h[(size_t)N_TOK * TOPK * HID];   // 256 MB hidden activations

// ---------------- async-copy helpers ----------------
__device__ __forceinline__ unsigned smem_u32(const void* p) {
    return (unsigned)__cvta_generic_to_shared(p);
}
__device__ __forceinline__ void cp_async16(unsigned dst, const void* src, int src_bytes) {
    asm volatile("cp.async.cg.shared.global [%0], [%1], 16, %2;\n"
                 :: "r"(dst), "l"(src), "r"(src_bytes));
}
__device__ __forceinline__ void cp_commit() {
    asm volatile("cp.async.commit_group;\n");
}
template <int N>
__device__ __forceinline__ void cp_wait() {
    asm volatile("cp.async.wait_group %0;\n" :: "n"(N));
}

// ---------------- init: zero output + counters ----------------
__global__ void init_kernel(float* __restrict__ out) {
    size_t i = (size_t)blockIdx.x * blockDim.x + threadIdx.x;
    if (i < (size_t)N_TOK * DIM / 4) {
        ((float4*)out)[i] = make_float4(0.f, 0.f, 0.f, 0.f);
    }
    if (blockIdx.x == 0 && threadIdx.x < NE) {
        g_counts[threadIdx.x] = 0;
        g_cursor[threadIdx.x] = 0;
    }
}

// ---------------- gating: warp per token ----------------
__global__ void gate_kernel(const float* __restrict__ x,
                            const float* __restrict__ gw,
                            const float* __restrict__ gb) {
    int warp = threadIdx.x >> 5;
    int lane = threadIdx.x & 31;
    int n = blockIdx.x * (blockDim.x >> 5) + warp;
    if (n >= N_TOK) return;

    float acc[NE];
#pragma unroll
    for (int e = 0; e < NE; e++) acc[e] = 0.f;

    const float* xr = x + (size_t)n * DIM;
    for (int d = lane; d < DIM; d += 32) {
        float xv = xr[d];
        float4 w0 = *(const float4*)(gw + (size_t)d * NE);
        float4 w1 = *(const float4*)(gw + (size_t)d * NE + 4);
        acc[0] += xv * w0.x; acc[1] += xv * w0.y;
        acc[2] += xv * w0.z; acc[3] += xv * w0.w;
        acc[4] += xv * w1.x; acc[5] += xv * w1.y;
        acc[6] += xv * w1.z; acc[7] += xv * w1.w;
    }
#pragma unroll
    for (int e = 0; e < NE; e++) {
#pragma unroll
        for (int o = 16; o; o >>= 1)
            acc[e] += __shfl_down_sync(0xffffffffu, acc[e], o);
    }

    if (lane == 0) {
        float v[NE];
#pragma unroll
        for (int e = 0; e < NE; e++) v[e] = acc[e] + gb[e];
        int i0 = 0;
#pragma unroll
        for (int e = 1; e < NE; e++) if (v[e] > v[i0]) i0 = e;
        int i1 = -1;
#pragma unroll
        for (int e = 0; e < NE; e++) {
            if (e == i0) continue;
            if (i1 < 0 || v[e] > v[i1]) i1 = e;
        }
        float t  = expf(v[i1] - v[i0]);
        float w0 = 1.f / (1.f + t);
        float w1 = t / (1.f + t);

        g_tok_e[n * 2]     = i0;
        g_tok_e[n * 2 + 1] = i1;
        g_tok_w[n * 2]     = w0;
        g_tok_w[n * 2 + 1] = w1;
        atomicAdd(&g_counts[i0], 1);
        atomicAdd(&g_counts[i1], 1);
    }
}

// ---------------- scan: exclusive prefix over 8 experts ----------------
__global__ void scan_kernel() {
    if (threadIdx.x == 0) {
        int s = 0;
        for (int e = 0; e < NE; e++) {
            g_offsets[e] = s;
            s += g_counts[e];
            g_cursor[e] = 0;
        }
    }
}

// ---------------- scatter tokens into per-expert buckets ----------------
__global__ void scatter_kernel() {
    int n = blockIdx.x * blockDim.x + threadIdx.x;
    if (n >= N_TOK) return;
#pragma unroll
    for (int k = 0; k < TOPK; k++) {
        int e = g_tok_e[n * 2 + k];
        int p = atomicAdd(&g_cursor[e], 1);
        int s = g_offsets[e] + p;
        g_btok[s] = n;
        g_bw[s]   = g_tok_w[n * 2 + k];
    }
}

// ---------------- grouped GEMM, 128x128x32 tiles, 3-stage cp.async ----------------
// MODE 0: h = gelu_tanh(gather(x) @ w1[e] + b1[e])     -> g_h
// MODE 1: out[token] += w * (h @ w2[e] + b2[e])        (atomic scatter)
template <int MODE>
__global__ void __launch_bounds__(256)
expert_gemm(const float* __restrict__ X,     // x (mode0) / unused (mode1)
            const float* __restrict__ W,     // w1 or w2 base [E, Kdim, Ncols]
            const float* __restrict__ bias,  // b1 or b2 base [E, Ncols]
            float* __restrict__ out,         // final out (mode1)
            int Kdim, int Ncols) {
    int e    = blockIdx.z;
    int cnt  = g_counts[e];
    int row0 = blockIdx.y * BM;
    if (row0 >= cnt) return;
    int col0 = blockIdx.x * BN;
    int off  = g_offsets[e];
    const float* Wb = W + (size_t)e * Kdim * Ncols + col0;

    extern __shared__ float smem[];
    int tid  = threadIdx.x;
    int warp = tid >> 5;
    int wr   = warp >> 2;   // 0..1  (64-row block)
    int wc   = warp & 3;    // 0..3  (32-col block)

    // --- hoist A-gather pointers (4 rows/thread, fixed across k) ---
    int a_c4 = tid & 7;      // float4 col within BK
    int a_r0 = tid >> 3;     // 0..31
    const float* a_src[4];
    int a_bytes[4];
#pragma unroll
    for (int it = 0; it < 4; it++) {
        int r  = a_r0 + 32 * it;
        int gr = row0 + r;
        bool ok = gr < cnt;
        const float* p;
        if (MODE == 0) {
            int t = ok ? g_btok[off + gr] : 0;
            p = X + (size_t)t * Kdim + a_c4 * 4;
        } else {
            p = g_h + (size_t)(off + (ok ? gr : 0)) * Kdim + a_c4 * 4;
        }
        a_src[it]   = p;
        a_bytes[it] = ok ? 16 : 0;
    }
    // --- B pointers (4 float4/thread) ---
    int b_c4 = tid & 31;     // float4 col within BN
    int b_r0 = tid >> 5;     // 0..7
    const float* b_src[4];
#pragma unroll
    for (int it = 0; it < 4; it++) {
        b_src[it] = Wb + (size_t)(b_r0 + 8 * it) * Ncols + b_c4 * 4;
    }

    auto load_stage = [&](int s, int k0) {
        float* base = smem + s * STAGE_FLOATS;
        unsigned sa = smem_u32(base);
        unsigned sb = smem_u32(base + BM * LDA);
#pragma unroll
        for (int it = 0; it < 4; it++) {
            int r = a_r0 + 32 * it;
            cp_async16(sa + (r * LDA + a_c4 * 4) * 4, a_src[it] + k0, a_bytes[it]);
        }
#pragma unroll
        for (int it = 0; it < 4; it++) {
            int r = b_r0 + 8 * it;
            cp_async16(sb + (r * LDB + b_c4 * 4) * 4, b_src[it] + (size_t)k0 * Ncols, 16);
        }
        cp_commit();
    };

    wmma::fragment<wmma::accumulator, 16, 16, 8, float> acc[4][2];
#pragma unroll
    for (int i = 0; i < 4; i++)
#pragma unroll
        for (int j = 0; j < 2; j++)
            wmma::fill_fragment(acc[i][j], 0.f);

    int KT = Kdim / BK;
    load_stage(0, 0);
    load_stage(1, BK);

    for (int k = 0; k < KT; k++) {
        if (k + 1 < KT) cp_wait<1>(); else cp_wait<0>();
        __syncthreads();
        if (k + 2 < KT) load_stage((k + 2) % STAGES, (k + 2) * BK);

        float* base = smem + (k % STAGES) * STAGE_FLOATS;
        float* sA = base;
        float* sB = base + BM * LDA;

#pragma unroll
        for (int kk = 0; kk < BK; kk += 8) {
            wmma::fragment<wmma::matrix_a, 16, 16, 8, wmma::precision::tf32, wmma::row_major> af[4];
            wmma::fragment<wmma::matrix_b, 16, 16, 8, wmma::precision::tf32, wmma::row_major> bf[2];
#pragma unroll
            for (int i = 0; i < 4; i++) {
                wmma::load_matrix_sync(af[i], &sA[(wr * 64 + i * 16) * LDA + kk], LDA);
#pragma unroll
                for (int t = 0; t < af[i].num_elements; t++)
                    af[i].x[t] = wmma::__float_to_tf32(af[i].x[t]);
            }
#pragma unroll
            for (int j = 0; j < 2; j++) {
                wmma::load_matrix_sync(bf[j], &sB[kk * LDB + wc * 32 + j * 16], LDB);
#pragma unroll
                for (int t = 0; t < bf[j].num_elements; t++)
                    bf[j].x[t] = wmma::__float_to_tf32(bf[j].x[t]);
            }
#pragma unroll
            for (int i = 0; i < 4; i++)
#pragma unroll
                for (int j = 0; j < 2; j++)
                    wmma::mma_sync(acc[i][j], af[i], bf[j], acc[i][j]);
        }
    }

    // --- epilogue: stage C in smem (reuse pipeline smem), then fused bias/act ---
    __syncthreads();
#pragma unroll
    for (int i = 0; i < 4; i++)
#pragma unroll
        for (int j = 0; j < 2; j++)
            wmma::store_matrix_sync(&smem[(wr * 64 + i * 16) * LDC + wc * 32 + j * 16],
                                    acc[i][j], LDC, wmma::mem_row_major);
    __syncthreads();

    const float* bias_e = bias + (size_t)e * Ncols + col0;
#pragma unroll
    for (int it = 0; it < 16; it++) {
        int idx = tid + it * 256;        // 0..4095 (float4 index)
        int r   = idx >> 5;
        int c4  = idx & 31;
        int gr  = row0 + r;
        if (gr >= cnt) continue;
        float4 v = *(float4*)&smem[r * LDC + c4 * 4];
        float4 b = *(const float4*)(bias_e + c4 * 4);
        v.x += b.x; v.y += b.y; v.z += b.z; v.w += b.w;
        if (MODE == 0) {
            float* g = &v.x;
#pragma unroll
            for (int q = 0; q < 4; q++) {
                float u = g[q];
                g[q] = 0.5f * u * (1.f + tanhf(0.7978845608028654f * (u + 0.044715f * u * u * u)));
            }
            *(float4*)&g_h[(size_t)(off + gr) * Ncols + col0 + c4 * 4] = v;
        } else {
            int   t = g_btok[off + gr];
            float w = g_bw[off + gr];
            float* o = out + (size_t)t * Ncols + col0 + c4 * 4;
            atomicAdd(o + 0, w * v.x);
            atomicAdd(o + 1, w * v.y);
            atomicAdd(o + 2, w * v.z);
            atomicAdd(o + 3, w * v.w);
        }
    }
}

// ---------------- launch ----------------
extern "C" void kernel_launch(void* const* d_in, const int* in_sizes, int n_in,
                              void* d_out, int out_size) {
    (void)in_sizes; (void)n_in; (void)out_size;
    const float* x  = (const float*)d_in[0];
    const float* gw = (const float*)d_in[1];
    const float* gb = (const float*)d_in[2];
    const float* w1 = (const float*)d_in[3];
    const float* b1 = (const float*)d_in[4];
    const float* w2 = (const float*)d_in[5];
    const float* b2 = (const float*)d_in[6];
    float* out = (float*)d_out;

    // Idempotent, non-stream attribute set on every call (no static guards).
    cudaFuncSetAttribute(expert_gemm<0>, cudaFuncAttributeMaxDynamicSharedMemorySize, GEMM_SMEM_BYTES);
    cudaFuncSetAttribute(expert_gemm<1>, cudaFuncAttributeMaxDynamicSharedMemorySize, GEMM_SMEM_BYTES);

    init_kernel<<<(N_TOK * DIM / 4 + 255) / 256, 256>>>(out);
    gate_kernel<<<N_TOK / 8, 256>>>(x, gw, gb);
    scan_kernel<<<1, 32>>>();
    scatter_kernel<<<(N_TOK + 255) / 256, 256>>>();

    dim3 g1(HID / BN, N_TOK / BM, NE);
    expert_gemm<0><<<g1, 256, GEMM_SMEM_BYTES>>>(x, w1, b1, out, DIM, HID);
    dim3 g2(DIM / BN, N_TOK / BM, NE);
    expert_gemm<1><<<g2, 256, GEMM_SMEM_BYTES>>>(nullptr, w2, b2, out, HID, DIM);
}